// round 6
// baseline (speedup 1.0000x reference)
#include <cuda_runtime.h>
#include <cuda_bf16.h>
#include <cstdint>

#define D 128
#define NMAX 50000
#define NPAD 50176   // >= 391*128; pad rows of scratch stay zero (never written)

// ---------------------------------------------------------------------------
// Scratch (__device__ globals per allocation rules)
// ---------------------------------------------------------------------------
__device__ __align__(16) float         g_agg[NPAD * D];   // neighbor sum (zeroed each run)
__device__ __align__(16) __nv_bfloat16 g_y1h[NPAD * D];   // hidden hi
__device__ __align__(16) __nv_bfloat16 g_y1l[NPAD * D];   // hidden lo
__device__ __align__(16) __nv_bfloat16 g_w1tH[D * D];     // W1^T hi [col][k]
__device__ __align__(16) __nv_bfloat16 g_w1tL[D * D];     // W1^T lo
__device__ __align__(16) __nv_bfloat16 g_w2tH[D * D];     // W2^T hi
__device__ __align__(16) __nv_bfloat16 g_w2tL[D * D];     // W2^T lo
__device__ __align__(16) float         g_stats[2 * D];    // col sum/sumsq -> scale/shift

// ---------------------------------------------------------------------------
// PTX helpers (portable ISA only — tcgen05 unavailable on compute_103 target)
// ---------------------------------------------------------------------------
__device__ __forceinline__ void cp16(uint32_t dst, const void* src) {
    asm volatile("cp.async.cg.shared.global [%0], [%1], 16;" :: "r"(dst), "l"(src));
}
__device__ __forceinline__ void cp_commit() { asm volatile("cp.async.commit_group;"); }
template <int N>
__device__ __forceinline__ void cp_wait() {
    asm volatile("cp.async.wait_group %0;" :: "n"(N));
}
__device__ __forceinline__ uint32_t smem_u32(const void* p) {
    return (uint32_t)__cvta_generic_to_shared(p);
}
__device__ __forceinline__ void mma16816(float* c, const uint32_t* a, const uint32_t* b) {
    asm volatile(
        "mma.sync.aligned.m16n8k16.row.col.f32.bf16.bf16.f32 "
        "{%0,%1,%2,%3}, {%4,%5,%6,%7}, {%8,%9}, {%0,%1,%2,%3};"
        : "+f"(c[0]), "+f"(c[1]), "+f"(c[2]), "+f"(c[3])
        : "r"(a[0]), "r"(a[1]), "r"(a[2]), "r"(a[3]), "r"(b[0]), "r"(b[1]));
}
__device__ __forceinline__ void ldsm4(uint32_t* r, uint32_t addr) {
    asm volatile("ldmatrix.sync.aligned.m8n8.x4.shared.b16 {%0,%1,%2,%3}, [%4];"
                 : "=r"(r[0]), "=r"(r[1]), "=r"(r[2]), "=r"(r[3]) : "r"(addr));
}

// SMEM tiles: padded row stride 136 halves (272B) -> ldmatrix row addresses hit
// distinct bank quads (68 mod 32 = 4), conflict-free.
#define SH 136
#define TILE_A (128 * SH * 2)   // 34816 B (one of hi/lo)
#define TILE_B (64 * SH * 2)    // 17408 B (one of hi/lo)
#define SMEM_GEMM (2 * TILE_A + 2 * TILE_B + 256)   // + 64-float bias slice

// ---------------------------------------------------------------------------
// Kernel 1: zero aggregation buffer + BN stats
// ---------------------------------------------------------------------------
__global__ void k_zero(int n4) {
    int i = blockIdx.x * blockDim.x + threadIdx.x;
    if (i < n4) reinterpret_cast<float4*>(g_agg)[i] = make_float4(0.f, 0.f, 0.f, 0.f);
    if (blockIdx.x == 0 && threadIdx.x < 2 * D) g_stats[threadIdx.x] = 0.0f;
}

// ---------------------------------------------------------------------------
// Kernel 2: transpose + bf16-split both weight matrices (one-shot, tiny)
// ---------------------------------------------------------------------------
__global__ void k_wt(const float* __restrict__ W1, const float* __restrict__ W2) {
    int i = blockIdx.x * 256 + threadIdx.x;
    if (i < D * D) {
        int k = i >> 7, c = i & 127;
        float w1 = W1[i], w2 = W2[i];
        __nv_bfloat16 h1 = __float2bfloat16(w1);
        __nv_bfloat16 h2 = __float2bfloat16(w2);
        g_w1tH[c * D + k] = h1;
        g_w1tL[c * D + k] = __float2bfloat16(w1 - __bfloat162float(h1));
        g_w2tH[c * D + k] = h2;
        g_w2tL[c * D + k] = __float2bfloat16(w2 - __bfloat162float(h2));
    }
}

// ---------------------------------------------------------------------------
// Kernel 3: scatter-add. One warp per edge; red.global.add.v4.f32 per lane.
// ---------------------------------------------------------------------------
__global__ void k_scatter(const float* __restrict__ feat,
                          const int* __restrict__ ei, int E) {
    int gw = (blockIdx.x * blockDim.x + threadIdx.x) >> 5;
    int lane = threadIdx.x & 31;
    if (gw >= E) return;
    int src = __ldg(ei + gw);
    int dst = __ldg(ei + E + gw);
    const float4 v = reinterpret_cast<const float4*>(feat + (size_t)src * D)[lane];
    float* p = g_agg + (size_t)dst * D + lane * 4;
    asm volatile("red.global.add.v4.f32 [%0], {%1, %2, %3, %4};"
                 :: "l"(p), "f"(v.x), "f"(v.y), "f"(v.z), "f"(v.w)
                 : "memory");
}

// ---------------------------------------------------------------------------
// Kernel 4/5: tensor-core GEMM via mma.sync + ldmatrix.
// Block tile 128 rows x 64 cols (grid.y = 2 col halves), 8 warps, warp 32x32.
// 3-term split AhWh + AhWl + AlWh, 24 k16 steps.
// FIRST: A = feat+agg converted in prologue, out -> y1 hi/lo.
// !FIRST: A = y1 hi/lo via cp.async, out -> d_out f32 + fused BN stats.
// ---------------------------------------------------------------------------
template <bool FIRST>
__global__ __launch_bounds__(256, 2)
void k_mma(const float* __restrict__ feat, const float* __restrict__ bias,
           float* __restrict__ outF, int M) {
    extern __shared__ __align__(16) uint8_t smem[];
    uint16_t* sAh = reinterpret_cast<uint16_t*>(smem);                    // 128 x SH
    uint16_t* sAl = reinterpret_cast<uint16_t*>(smem + TILE_A);
    uint16_t* sBh = reinterpret_cast<uint16_t*>(smem + 2 * TILE_A);      // 64 x SH
    uint16_t* sBl = reinterpret_cast<uint16_t*>(smem + 2 * TILE_A + TILE_B);
    float* s_bias = reinterpret_cast<float*>(smem + 2 * TILE_A + 2 * TILE_B);

    const __nv_bfloat16* __restrict__ Bh = FIRST ? g_w1tH : g_w2tH;
    const __nv_bfloat16* __restrict__ Bl = FIRST ? g_w1tL : g_w2tL;

    const int tid = threadIdx.x;
    const int wid = tid >> 5;
    const int lane = tid & 31;
    const int g = lane >> 2;
    const int l4 = lane & 3;
    const int warpM = wid & 3;       // 4 m-groups of 32 rows
    const int warpN = wid >> 2;      // 2 n-groups of 32 cols
    const int rowBase = blockIdx.x * 128;
    const int colBase = blockIdx.y * 64;

    if (tid < 64) s_bias[tid] = bias[colBase + tid];

    const uint32_t sBase = smem_u32(smem);

    // ---- B tiles (64 n-rows x 128 k, hi+lo) via cp.async ----
#pragma unroll
    for (int t = 0; t < 8; ++t) {
        int idx = tid + t * 256;            // 0..2047
        int tile = idx >> 10;               // 0=hi, 1=lo
        int row = (idx >> 4) & 63;
        int kb = (idx & 15) * 16;
        uint32_t dOff = (uint32_t)(2 * TILE_A + tile * TILE_B + row * (SH * 2) + kb);
        size_t gB = (size_t)(colBase + row) * 256 + kb;
        cp16(sBase + dOff, (const uint8_t*)(tile ? Bl : Bh) + gB);
    }
    cp_commit();

    // ---- A tiles ----
    if (FIRST) {
#pragma unroll
        for (int t = 0; t < 8; ++t) {
            int idx = tid + t * 256;        // 128 rows x 16 chunks
            int row = idx >> 4;
            int kc = (idx & 15) * 8;
            int grow = rowBase + row;
            float h[8];
            if (grow < M) {
                const float4* fp = reinterpret_cast<const float4*>(feat + (size_t)grow * D + kc);
                const float4* ap = reinterpret_cast<const float4*>(g_agg + (size_t)grow * D + kc);
                float4 f0 = fp[0], f1 = fp[1], a0 = ap[0], a1 = ap[1];
                h[0] = f0.x + a0.x; h[1] = f0.y + a0.y; h[2] = f0.z + a0.z; h[3] = f0.w + a0.w;
                h[4] = f1.x + a1.x; h[5] = f1.y + a1.y; h[6] = f1.z + a1.z; h[7] = f1.w + a1.w;
            } else {
#pragma unroll
                for (int e = 0; e < 8; ++e) h[e] = 0.f;
            }
            uint4 hv, lv;
            uint32_t* hp = reinterpret_cast<uint32_t*>(&hv);
            uint32_t* lp = reinterpret_cast<uint32_t*>(&lv);
#pragma unroll
            for (int e = 0; e < 4; ++e) {
                __nv_bfloat162 hh = __floats2bfloat162_rn(h[2 * e], h[2 * e + 1]);
                __nv_bfloat162 ll = __floats2bfloat162_rn(
                    h[2 * e] - __bfloat162float(hh.x),
                    h[2 * e + 1] - __bfloat162float(hh.y));
                hp[e] = *reinterpret_cast<uint32_t*>(&hh);
                lp[e] = *reinterpret_cast<uint32_t*>(&ll);
            }
            *reinterpret_cast<uint4*>(&sAh[row * SH + kc]) = hv;
            *reinterpret_cast<uint4*>(&sAl[row * SH + kc]) = lv;
        }
    } else {
#pragma unroll
        for (int t = 0; t < 16; ++t) {
            int idx = tid + t * 256;        // 0..4095: 2 tiles x 128 rows x 16 chunks
            int tile = idx >> 11;
            int row = (idx >> 4) & 127;
            int kb = (idx & 15) * 16;
            uint32_t dOff = (uint32_t)(tile * TILE_A + row * (SH * 2) + kb);
            size_t gA = (size_t)(rowBase + row) * 256 + kb;
            cp16(sBase + dOff, (const uint8_t*)(tile ? g_y1l : g_y1h) + gA);
        }
        cp_commit();
    }
    cp_wait<0>();
    __syncthreads();

    // ---- ldmatrix address offsets (bytes, relative to tile start) ----
    // A fragments (16x16): m0..m3 = (row0..7,k0) (row8..15,k0) (row0..7,k8) (row8..15,k8)
    uint32_t aOff[2], bOff[2];
#pragma unroll
    for (int mi = 0; mi < 2; ++mi) {
        int arow = warpM * 32 + mi * 16 + (lane & 7) + ((lane >> 3) & 1) * 8;
        int akoff = (lane >> 4) * 8;
        aOff[mi] = (uint32_t)((arow * SH + akoff) * 2);
    }
    // B fragments (two n8k16 tiles per x4): m0,m1 = rows0-7 (k0,k8); m2,m3 = rows8-15
#pragma unroll
    for (int pr = 0; pr < 2; ++pr) {
        int brow = warpN * 32 + pr * 16 + (lane & 7) + (lane >> 4) * 8;
        int bkoff = ((lane >> 3) & 1) * 8;
        bOff[pr] = (uint32_t)(2 * TILE_A + (brow * SH + bkoff) * 2);
    }

    float c[2][4][4];
#pragma unroll
    for (int mi = 0; mi < 2; ++mi)
#pragma unroll
        for (int ni = 0; ni < 4; ++ni)
#pragma unroll
            for (int e = 0; e < 4; ++e) c[mi][ni][e] = 0.f;

#pragma unroll
    for (int pass = 0; pass < 3; ++pass) {
        const uint32_t aBase = sBase + (pass == 2 ? TILE_A : 0);
        const uint32_t bBase = sBase + (pass == 1 ? TILE_B : 0);
#pragma unroll
        for (int ks = 0; ks < 8; ++ks) {
            uint32_t a[2][4], b[2][4];   // b[pr] = {b[2pr][0], b[2pr][1], b[2pr+1][0], b[2pr+1][1]}
            ldsm4(a[0], aBase + aOff[0] + ks * 32);
            ldsm4(a[1], aBase + aOff[1] + ks * 32);
            ldsm4(b[0], bBase + bOff[0] + ks * 32);
            ldsm4(b[1], bBase + bOff[1] + ks * 32);
#pragma unroll
            for (int mi = 0; mi < 2; ++mi) {
                mma16816(c[mi][0], a[mi], &b[0][0]);
                mma16816(c[mi][1], a[mi], &b[0][2]);
                mma16816(c[mi][2], a[mi], &b[1][0]);
                mma16816(c[mi][3], a[mi], &b[1][2]);
            }
        }
    }

    // ---- Epilogue ----
    float cs[4][2], cq[4][2];
    if (!FIRST) {
#pragma unroll
        for (int ni = 0; ni < 4; ++ni) {
            cs[ni][0] = cs[ni][1] = 0.f;
            cq[ni][0] = cq[ni][1] = 0.f;
        }
    }

#pragma unroll
    for (int mi = 0; mi < 2; ++mi) {
#pragma unroll
        for (int half = 0; half < 2; ++half) {
            const int row = rowBase + warpM * 32 + mi * 16 + g + half * 8;
            if (row < M) {
#pragma unroll
                for (int ni = 0; ni < 4; ++ni) {
                    const int ccol = warpN * 32 + ni * 8 + 2 * l4;   // 0..63 in block
                    const int col = colBase + ccol;
                    float v0 = fmaxf(c[mi][ni][half * 2 + 0] + s_bias[ccol], 0.f);
                    float v1 = fmaxf(c[mi][ni][half * 2 + 1] + s_bias[ccol + 1], 0.f);
                    if (FIRST) {
                        __nv_bfloat16 h0 = __float2bfloat16(v0);
                        __nv_bfloat16 h1 = __float2bfloat16(v1);
                        __nv_bfloat162 hh; hh.x = h0; hh.y = h1;
                        __nv_bfloat162 ll = __floats2bfloat162_rn(
                            v0 - __bfloat162float(h0), v1 - __bfloat162float(h1));
                        size_t bo = (size_t)row * 256 + (size_t)col * 2;
                        *reinterpret_cast<uint32_t*>((uint8_t*)g_y1h + bo) =
                            *reinterpret_cast<uint32_t*>(&hh);
                        *reinterpret_cast<uint32_t*>((uint8_t*)g_y1l + bo) =
                            *reinterpret_cast<uint32_t*>(&ll);
                    } else {
                        float2 st; st.x = v0; st.y = v1;
                        *reinterpret_cast<float2*>(outF + (size_t)row * D + col) = st;
                        cs[ni][0] += v0; cs[ni][1] += v1;
                        cq[ni][0] += v0 * v0; cq[ni][1] += v1 * v1;
                    }
                }
            }
        }
    }

    if (!FIRST) {
        // reduce over g-lanes (bits 2..4) via shfl_xor
#pragma unroll
        for (int off = 4; off < 32; off <<= 1) {
#pragma unroll
            for (int ni = 0; ni < 4; ++ni) {
#pragma unroll
                for (int e = 0; e < 2; ++e) {
                    cs[ni][e] += __shfl_xor_sync(0xFFFFFFFFu, cs[ni][e], off);
                    cq[ni][e] += __shfl_xor_sync(0xFFFFFFFFu, cq[ni][e], off);
                }
            }
        }
        __syncthreads();                 // tiles dead; reuse as reduction buffer
        float* redS = reinterpret_cast<float*>(smem);        // [8][32]
        float* redQ = redS + 8 * 32;                         // [8][32]
        if (g == 0) {
#pragma unroll
            for (int ni = 0; ni < 4; ++ni) {
#pragma unroll
                for (int e = 0; e < 2; ++e) {
                    int cc = ni * 8 + 2 * l4 + e;            // 0..31 within warpN half
                    redS[wid * 32 + cc] = cs[ni][e];
                    redQ[wid * 32 + cc] = cq[ni][e];
                }
            }
        }
        __syncthreads();
        if (tid < 64) {
            int wN = tid >> 5;           // which warpN half
            int cc = tid & 31;
            float s = 0.f, q = 0.f;
#pragma unroll
            for (int w = 0; w < 4; ++w) {     // wid = wN*4 + w  (warpM 0..3)
                s += redS[(wN * 4 + w) * 32 + cc];
                q += redQ[(wN * 4 + w) * 32 + cc];
            }
            atomicAdd(&g_stats[colBase + tid], s);
            atomicAdd(&g_stats[D + colBase + tid], q);
        }
    }
}

// ---------------------------------------------------------------------------
// Kernel 6: (sum, sumsq) -> (scale, shift)
// ---------------------------------------------------------------------------
__global__ void k_finalize(const float* __restrict__ gamma,
                           const float* __restrict__ beta, float invN) {
    int c = threadIdx.x;
    float mean = g_stats[c] * invN;
    float var = g_stats[D + c] * invN - mean * mean;
    float scale = gamma[c] * rsqrtf(var + 1e-5f);
    g_stats[c] = scale;
    g_stats[D + c] = beta[c] - mean * scale;
}

// ---------------------------------------------------------------------------
// Kernel 7: out = out * scale[col] + shift[col], in place
// ---------------------------------------------------------------------------
__global__ void k_norm(float4* __restrict__ out, int n4) {
    int i = blockIdx.x * blockDim.x + threadIdx.x;
    if (i >= n4) return;
    int c4 = (i & 31) * 4;
    float4 sc = *reinterpret_cast<const float4*>(&g_stats[c4]);
    float4 sh = *reinterpret_cast<const float4*>(&g_stats[D + c4]);
    float4 v = out[i];
    v.x = v.x * sc.x + sh.x;
    v.y = v.y * sc.y + sh.y;
    v.z = v.z * sc.z + sh.z;
    v.w = v.w * sc.w + sh.w;
    out[i] = v;
}

// ---------------------------------------------------------------------------
extern "C" void kernel_launch(void* const* d_in, const int* in_sizes, int n_in,
                              void* d_out, int out_size) {
    const float* feat  = (const float*)d_in[0];
    const int*   ei    = (const int*)d_in[1];
    const float* W1    = (const float*)d_in[2];
    const float* b1    = (const float*)d_in[3];
    const float* W2    = (const float*)d_in[4];
    const float* b2    = (const float*)d_in[5];
    const float* gamma = (const float*)d_in[6];
    const float* beta  = (const float*)d_in[7];
    float* out = (float*)d_out;

    const int N = in_sizes[0] / D;     // 50000
    const int E = in_sizes[1] / 2;     // 600000
    const int n4 = N * D / 4;

    cudaFuncSetAttribute(k_mma<true>, cudaFuncAttributeMaxDynamicSharedMemorySize, SMEM_GEMM);
    cudaFuncSetAttribute(k_mma<false>, cudaFuncAttributeMaxDynamicSharedMemorySize, SMEM_GEMM);

    k_zero<<<(n4 + 255) / 256, 256>>>(n4);
    k_wt<<<(D * D + 255) / 256, 256>>>(W1, W2);
    {
        long long totalThreads = (long long)E * 32;
        int blocks = (int)((totalThreads + 255) / 256);
        k_scatter<<<blocks, 256>>>(feat, ei, E);
    }
    int gb = (N + 127) / 128;          // 391
    dim3 gg(gb, 2);
    k_mma<true><<<gg, 256, SMEM_GEMM>>>(feat, b1, nullptr, N);
    k_mma<false><<<gg, 256, SMEM_GEMM>>>(nullptr, b2, out, N);
    k_finalize<<<1, 128>>>(gamma, beta, 1.0f / (float)N);
    k_norm<<<(n4 + 255) / 256, 256>>>((float4*)out, n4);
}

// round 7
// speedup vs baseline: 1.0324x; 1.0324x over previous
#include <cuda_runtime.h>
#include <cuda_bf16.h>
#include <cstdint>

#define D 128
#define NMAX 50000
#define NPAD 50176   // multiple of 64; pad rows stay zero (never written)

// ---------------------------------------------------------------------------
// Scratch (__device__ globals per allocation rules)
// ---------------------------------------------------------------------------
__device__ __align__(16) float         g_agg[NPAD * D];   // neighbor sum (zeroed each run)
__device__ __align__(16) __nv_bfloat16 g_y1h[NPAD * D];   // hidden hi
__device__ __align__(16) __nv_bfloat16 g_y1l[NPAD * D];   // hidden lo
__device__ __align__(16) __nv_bfloat16 g_w1tH[D * D];     // W1^T hi [col][k]
__device__ __align__(16) __nv_bfloat16 g_w1tL[D * D];     // W1^T lo
__device__ __align__(16) __nv_bfloat16 g_w2tH[D * D];     // W2^T hi
__device__ __align__(16) __nv_bfloat16 g_w2tL[D * D];     // W2^T lo
__device__ __align__(16) float         g_stats[2 * D];    // col sum/sumsq -> scale/shift

// ---------------------------------------------------------------------------
// PTX helpers (portable ISA only — tcgen05 unavailable on compute_103 target)
// ---------------------------------------------------------------------------
__device__ __forceinline__ void cp16(uint32_t dst, const void* src) {
    asm volatile("cp.async.cg.shared.global [%0], [%1], 16;" :: "r"(dst), "l"(src));
}
__device__ __forceinline__ void cp_commit() { asm volatile("cp.async.commit_group;"); }
template <int N>
__device__ __forceinline__ void cp_wait() {
    asm volatile("cp.async.wait_group %0;" :: "n"(N));
}
__device__ __forceinline__ uint32_t smem_u32(const void* p) {
    return (uint32_t)__cvta_generic_to_shared(p);
}
__device__ __forceinline__ void mma16816(float* c, const uint32_t* a, const uint32_t* b) {
    asm volatile(
        "mma.sync.aligned.m16n8k16.row.col.f32.bf16.bf16.f32 "
        "{%0,%1,%2,%3}, {%4,%5,%6,%7}, {%8,%9}, {%0,%1,%2,%3};"
        : "+f"(c[0]), "+f"(c[1]), "+f"(c[2]), "+f"(c[3])
        : "r"(a[0]), "r"(a[1]), "r"(a[2]), "r"(a[3]), "r"(b[0]), "r"(b[1]));
}
__device__ __forceinline__ void ldsm4(uint32_t* r, uint32_t addr) {
    asm volatile("ldmatrix.sync.aligned.m8n8.x4.shared.b16 {%0,%1,%2,%3}, [%4];"
                 : "=r"(r[0]), "=r"(r[1]), "=r"(r[2]), "=r"(r[3]) : "r"(addr));
}

// Padded row stride 136 halves (272B): ldmatrix row addresses hit distinct
// bank quads (68 mod 32 = 4), conflict-free.
#define SH 136
#define TILE_A (64 * SH * 2)     // 17408 B (A: 64 rows, one of hi/lo)
#define TILE_B (128 * SH * 2)    // 34816 B (B: 128 cols, one of hi/lo)
#define SMEM_GEMM (2 * TILE_A + 2 * TILE_B + 512)   // + 128-float bias

// ---------------------------------------------------------------------------
// Kernel 1: zero aggregation buffer + BN stats
// ---------------------------------------------------------------------------
__global__ void k_zero(int n4) {
    int i = blockIdx.x * blockDim.x + threadIdx.x;
    if (i < n4) reinterpret_cast<float4*>(g_agg)[i] = make_float4(0.f, 0.f, 0.f, 0.f);
    if (blockIdx.x == 0 && threadIdx.x < 2 * D) g_stats[threadIdx.x] = 0.0f;
}

// ---------------------------------------------------------------------------
// Kernel 2: transpose + bf16-split both weight matrices (one-shot, tiny)
// ---------------------------------------------------------------------------
__global__ void k_wt(const float* __restrict__ W1, const float* __restrict__ W2) {
    int i = blockIdx.x * 256 + threadIdx.x;
    if (i < D * D) {
        int k = i >> 7, c = i & 127;
        float w1 = W1[i], w2 = W2[i];
        __nv_bfloat16 h1 = __float2bfloat16(w1);
        __nv_bfloat16 h2 = __float2bfloat16(w2);
        g_w1tH[c * D + k] = h1;
        g_w1tL[c * D + k] = __float2bfloat16(w1 - __bfloat162float(h1));
        g_w2tH[c * D + k] = h2;
        g_w2tL[c * D + k] = __float2bfloat16(w2 - __bfloat162float(h2));
    }
}

// ---------------------------------------------------------------------------
// Kernel 3: scatter-add. One warp per edge; red.global.add.v4.f32 per lane.
// ---------------------------------------------------------------------------
__global__ void k_scatter(const float* __restrict__ feat,
                          const int* __restrict__ ei, int E) {
    int gw = (blockIdx.x * blockDim.x + threadIdx.x) >> 5;
    int lane = threadIdx.x & 31;
    if (gw >= E) return;
    int src = __ldg(ei + gw);
    int dst = __ldg(ei + E + gw);
    const float4 v = reinterpret_cast<const float4*>(feat + (size_t)src * D)[lane];
    float* p = g_agg + (size_t)dst * D + lane * 4;
    asm volatile("red.global.add.v4.f32 [%0], {%1, %2, %3, %4};"
                 :: "l"(p), "f"(v.x), "f"(v.y), "f"(v.z), "f"(v.w)
                 : "memory");
}

// ---------------------------------------------------------------------------
// Kernel 4/5: tensor-core GEMM via mma.sync + ldmatrix.
// Block tile 64 rows x 128 cols (M-split only — A traffic never duplicated).
// 8 warps: warpM = wid&1 (32-row halves), warpN = wid>>1 (32-col quarters).
// 3-term split AhWh + AhWl + AlWh, 24 k16 steps, 2 CTAs/SM.
// FIRST: A = feat+agg converted in prologue, out -> y1 hi/lo.
// !FIRST: A = y1 hi/lo via cp.async, out -> d_out f32 + fused BN stats.
// ---------------------------------------------------------------------------
template <bool FIRST>
__global__ __launch_bounds__(256, 2)
void k_mma(const float* __restrict__ feat, const float* __restrict__ bias,
           float* __restrict__ outF, int M) {
    extern __shared__ __align__(16) uint8_t smem[];
    uint16_t* sAh = reinterpret_cast<uint16_t*>(smem);                    // 64 x SH
    uint16_t* sAl = reinterpret_cast<uint16_t*>(smem + TILE_A);
    float* s_bias = reinterpret_cast<float*>(smem + 2 * TILE_A + 2 * TILE_B);

    const __nv_bfloat16* __restrict__ Bh = FIRST ? g_w1tH : g_w2tH;
    const __nv_bfloat16* __restrict__ Bl = FIRST ? g_w1tL : g_w2tL;

    const int tid = threadIdx.x;
    const int wid = tid >> 5;
    const int lane = tid & 31;
    const int g = lane >> 2;
    const int l4 = lane & 3;
    const int warpM = wid & 1;       // 2 m-groups of 32 rows
    const int warpN = wid >> 1;      // 4 n-groups of 32 cols
    const int rowBase = blockIdx.x * 64;

    if (tid < D) s_bias[tid] = bias[tid];

    const uint32_t sBase = smem_u32(smem);

    // ---- B tiles (128 n-rows x 128 k, hi+lo) via cp.async ----
#pragma unroll
    for (int t = 0; t < 16; ++t) {
        int idx = tid + t * 256;            // 0..4095
        int tile = idx >> 11;               // 0=hi, 1=lo
        int row = (idx >> 4) & 127;
        int kb = (idx & 15) * 16;
        uint32_t dOff = (uint32_t)(2 * TILE_A + tile * TILE_B + row * (SH * 2) + kb);
        size_t gB = (size_t)row * 256 + kb;
        cp16(sBase + dOff, (const uint8_t*)(tile ? Bl : Bh) + gB);
    }
    cp_commit();

    // ---- A tiles (64 rows) ----
    if (FIRST) {
#pragma unroll
        for (int t = 0; t < 4; ++t) {
            int idx = tid + t * 256;        // 64 rows x 16 chunks
            int row = idx >> 4;
            int kc = (idx & 15) * 8;
            int grow = rowBase + row;
            float h[8];
            if (grow < M) {
                const float4* fp = reinterpret_cast<const float4*>(feat + (size_t)grow * D + kc);
                const float4* ap = reinterpret_cast<const float4*>(g_agg + (size_t)grow * D + kc);
                float4 f0 = fp[0], f1 = fp[1], a0 = ap[0], a1 = ap[1];
                h[0] = f0.x + a0.x; h[1] = f0.y + a0.y; h[2] = f0.z + a0.z; h[3] = f0.w + a0.w;
                h[4] = f1.x + a1.x; h[5] = f1.y + a1.y; h[6] = f1.z + a1.z; h[7] = f1.w + a1.w;
            } else {
#pragma unroll
                for (int e = 0; e < 8; ++e) h[e] = 0.f;
            }
            uint4 hv, lv;
            uint32_t* hp = reinterpret_cast<uint32_t*>(&hv);
            uint32_t* lp = reinterpret_cast<uint32_t*>(&lv);
#pragma unroll
            for (int e = 0; e < 4; ++e) {
                __nv_bfloat162 hh = __floats2bfloat162_rn(h[2 * e], h[2 * e + 1]);
                __nv_bfloat162 ll = __floats2bfloat162_rn(
                    h[2 * e] - __bfloat162float(hh.x),
                    h[2 * e + 1] - __bfloat162float(hh.y));
                hp[e] = *reinterpret_cast<uint32_t*>(&hh);
                lp[e] = *reinterpret_cast<uint32_t*>(&ll);
            }
            *reinterpret_cast<uint4*>(&sAh[row * SH + kc]) = hv;
            *reinterpret_cast<uint4*>(&sAl[row * SH + kc]) = lv;
        }
    } else {
#pragma unroll
        for (int t = 0; t < 8; ++t) {
            int idx = tid + t * 256;        // 2 tiles x 64 rows x 16 chunks
            int tile = idx >> 10;
            int row = (idx >> 4) & 63;
            int kb = (idx & 15) * 16;
            uint32_t dOff = (uint32_t)(tile * TILE_A + row * (SH * 2) + kb);
            size_t gA = (size_t)(rowBase + row) * 256 + kb;
            cp16(sBase + dOff, (const uint8_t*)(tile ? g_y1l : g_y1h) + gA);
        }
        cp_commit();
    }
    cp_wait<0>();
    __syncthreads();

    // ---- ldmatrix address offsets (bytes) ----
    uint32_t aOff[2], bOff[2];
#pragma unroll
    for (int mi = 0; mi < 2; ++mi) {
        int arow = warpM * 32 + mi * 16 + (lane & 7) + ((lane >> 3) & 1) * 8;
        int akoff = (lane >> 4) * 8;
        aOff[mi] = (uint32_t)((arow * SH + akoff) * 2);
    }
#pragma unroll
    for (int pr = 0; pr < 2; ++pr) {
        int brow = warpN * 32 + pr * 16 + (lane & 7) + (lane >> 4) * 8;
        int bkoff = ((lane >> 3) & 1) * 8;
        bOff[pr] = (uint32_t)(2 * TILE_A + (brow * SH + bkoff) * 2);
    }

    float c[2][4][4];
#pragma unroll
    for (int mi = 0; mi < 2; ++mi)
#pragma unroll
        for (int ni = 0; ni < 4; ++ni)
#pragma unroll
            for (int e = 0; e < 4; ++e) c[mi][ni][e] = 0.f;

#pragma unroll
    for (int pass = 0; pass < 3; ++pass) {
        const uint32_t aBase = sBase + (pass == 2 ? TILE_A : 0);
        const uint32_t bBase = sBase + (pass == 1 ? TILE_B : 0);
#pragma unroll
        for (int ks = 0; ks < 8; ++ks) {
            uint32_t a[2][4], b[2][4];
            ldsm4(a[0], aBase + aOff[0] + ks * 32);
            ldsm4(a[1], aBase + aOff[1] + ks * 32);
            ldsm4(b[0], bBase + bOff[0] + ks * 32);
            ldsm4(b[1], bBase + bOff[1] + ks * 32);
#pragma unroll
            for (int mi = 0; mi < 2; ++mi) {
                mma16816(c[mi][0], a[mi], &b[0][0]);
                mma16816(c[mi][1], a[mi], &b[0][2]);
                mma16816(c[mi][2], a[mi], &b[1][0]);
                mma16816(c[mi][3], a[mi], &b[1][2]);
            }
        }
    }

    // ---- Epilogue ----
    float cs[4][2], cq[4][2];
    if (!FIRST) {
#pragma unroll
        for (int ni = 0; ni < 4; ++ni) {
            cs[ni][0] = cs[ni][1] = 0.f;
            cq[ni][0] = cq[ni][1] = 0.f;
        }
    }

#pragma unroll
    for (int mi = 0; mi < 2; ++mi) {
#pragma unroll
        for (int half = 0; half < 2; ++half) {
            const int row = rowBase + warpM * 32 + mi * 16 + g + half * 8;
            if (row < M) {
#pragma unroll
                for (int ni = 0; ni < 4; ++ni) {
                    const int col = warpN * 32 + ni * 8 + 2 * l4;   // 0..127
                    float v0 = fmaxf(c[mi][ni][half * 2 + 0] + s_bias[col], 0.f);
                    float v1 = fmaxf(c[mi][ni][half * 2 + 1] + s_bias[col + 1], 0.f);
                    if (FIRST) {
                        __nv_bfloat16 h0 = __float2bfloat16(v0);
                        __nv_bfloat16 h1 = __float2bfloat16(v1);
                        __nv_bfloat162 hh; hh.x = h0; hh.y = h1;
                        __nv_bfloat162 ll = __floats2bfloat162_rn(
                            v0 - __bfloat162float(h0), v1 - __bfloat162float(h1));
                        size_t bo = (size_t)row * 256 + (size_t)col * 2;
                        *reinterpret_cast<uint32_t*>((uint8_t*)g_y1h + bo) =
                            *reinterpret_cast<uint32_t*>(&hh);
                        *reinterpret_cast<uint32_t*>((uint8_t*)g_y1l + bo) =
                            *reinterpret_cast<uint32_t*>(&ll);
                    } else {
                        float2 st; st.x = v0; st.y = v1;
                        *reinterpret_cast<float2*>(outF + (size_t)row * D + col) = st;
                        cs[ni][0] += v0; cs[ni][1] += v1;
                        cq[ni][0] += v0 * v0; cq[ni][1] += v1 * v1;
                    }
                }
            }
        }
    }

    if (!FIRST) {
        // reduce over g-lanes (bits 2..4) via shfl_xor
#pragma unroll
        for (int off = 4; off < 32; off <<= 1) {
#pragma unroll
            for (int ni = 0; ni < 4; ++ni) {
#pragma unroll
                for (int e = 0; e < 2; ++e) {
                    cs[ni][e] += __shfl_xor_sync(0xFFFFFFFFu, cs[ni][e], off);
                    cq[ni][e] += __shfl_xor_sync(0xFFFFFFFFu, cq[ni][e], off);
                }
            }
        }
        __syncthreads();                 // tiles dead; reuse as reduction buffer
        float* redS = reinterpret_cast<float*>(smem);        // [8][32]
        float* redQ = redS + 8 * 32;                         // [8][32]
        if (g == 0) {
#pragma unroll
            for (int ni = 0; ni < 4; ++ni) {
#pragma unroll
                for (int e = 0; e < 2; ++e) {
                    int cc = ni * 8 + 2 * l4 + e;            // 0..31 within warpN group
                    redS[wid * 32 + cc] = cs[ni][e];
                    redQ[wid * 32 + cc] = cq[ni][e];
                }
            }
        }
        __syncthreads();
        if (tid < 128) {
            int wN = tid >> 5;           // warpN group of this column
            int cc = tid & 31;
            float s = 0.f, q = 0.f;
#pragma unroll
            for (int w = 0; w < 2; ++w) {     // wid = wN*2 + warpM
                s += redS[(wN * 2 + w) * 32 + cc];
                q += redQ[(wN * 2 + w) * 32 + cc];
            }
            atomicAdd(&g_stats[tid], s);
            atomicAdd(&g_stats[D + tid], q);
        }
    }
}

// ---------------------------------------------------------------------------
// Kernel 6: (sum, sumsq) -> (scale, shift)
// ---------------------------------------------------------------------------
__global__ void k_finalize(const float* __restrict__ gamma,
                           const float* __restrict__ beta, float invN) {
    int c = threadIdx.x;
    float mean = g_stats[c] * invN;
    float var = g_stats[D + c] * invN - mean * mean;
    float scale = gamma[c] * rsqrtf(var + 1e-5f);
    g_stats[c] = scale;
    g_stats[D + c] = beta[c] - mean * scale;
}

// ---------------------------------------------------------------------------
// Kernel 7: out = out * scale[col] + shift[col], in place
// ---------------------------------------------------------------------------
__global__ void k_norm(float4* __restrict__ out, int n4) {
    int i = blockIdx.x * blockDim.x + threadIdx.x;
    if (i >= n4) return;
    int c4 = (i & 31) * 4;
    float4 sc = *reinterpret_cast<const float4*>(&g_stats[c4]);
    float4 sh = *reinterpret_cast<const float4*>(&g_stats[D + c4]);
    float4 v = out[i];
    v.x = v.x * sc.x + sh.x;
    v.y = v.y * sc.y + sh.y;
    v.z = v.z * sc.z + sh.z;
    v.w = v.w * sc.w + sh.w;
    out[i] = v;
}

// ---------------------------------------------------------------------------
extern "C" void kernel_launch(void* const* d_in, const int* in_sizes, int n_in,
                              void* d_out, int out_size) {
    const float* feat  = (const float*)d_in[0];
    const int*   ei    = (const int*)d_in[1];
    const float* W1    = (const float*)d_in[2];
    const float* b1    = (const float*)d_in[3];
    const float* W2    = (const float*)d_in[4];
    const float* b2    = (const float*)d_in[5];
    const float* gamma = (const float*)d_in[6];
    const float* beta  = (const float*)d_in[7];
    float* out = (float*)d_out;

    const int N = in_sizes[0] / D;     // 50000
    const int E = in_sizes[1] / 2;     // 600000
    const int n4 = N * D / 4;

    cudaFuncSetAttribute(k_mma<true>, cudaFuncAttributeMaxDynamicSharedMemorySize, SMEM_GEMM);
    cudaFuncSetAttribute(k_mma<false>, cudaFuncAttributeMaxDynamicSharedMemorySize, SMEM_GEMM);

    k_zero<<<(n4 + 255) / 256, 256>>>(n4);
    k_wt<<<(D * D + 255) / 256, 256>>>(W1, W2);
    {
        long long totalThreads = (long long)E * 32;
        int blocks = (int)((totalThreads + 255) / 256);
        k_scatter<<<blocks, 256>>>(feat, ei, E);
    }
    int gb = (N + 63) / 64;            // 782 row tiles
    k_mma<true><<<gb, 256, SMEM_GEMM>>>(feat, b1, nullptr, N);
    k_mma<false><<<gb, 256, SMEM_GEMM>>>(nullptr, b2, out, N);
    k_finalize<<<1, 128>>>(gamma, beta, 1.0f / (float)N);
    k_norm<<<(n4 + 255) / 256, 256>>>((float4*)out, n4);
}

// round 8
// speedup vs baseline: 1.2462x; 1.2070x over previous
#include <cuda_runtime.h>
#include <cuda_bf16.h>
#include <cstdint>

#define D 128
#define NMAX 50000
#define NPAD 50176

// ---------------------------------------------------------------------------
// Scratch (__device__ globals per allocation rules)
// ---------------------------------------------------------------------------
__device__ __align__(16) float         g_agg[NPAD * D];   // neighbor sum (zeroed each run)
__device__ __align__(16) __nv_bfloat16 g_w1tH[D * D];     // W1^T hi [col][k]
__device__ __align__(16) __nv_bfloat16 g_w1tL[D * D];     // W1^T lo
__device__ __align__(16) __nv_bfloat16 g_w2tH[D * D];     // W2^T hi
__device__ __align__(16) __nv_bfloat16 g_w2tL[D * D];     // W2^T lo
__device__ __align__(16) float         g_stats[2 * D];    // col sum/sumsq -> scale/shift

// ---------------------------------------------------------------------------
// PTX helpers (portable ISA only — tcgen05 unavailable on compute_103 target)
// ---------------------------------------------------------------------------
__device__ __forceinline__ void cp16(uint32_t dst, const void* src) {
    asm volatile("cp.async.cg.shared.global [%0], [%1], 16;" :: "r"(dst), "l"(src));
}
__device__ __forceinline__ void cp_commit() { asm volatile("cp.async.commit_group;"); }
template <int N>
__device__ __forceinline__ void cp_wait() {
    asm volatile("cp.async.wait_group %0;" :: "n"(N));
}
__device__ __forceinline__ uint32_t smem_u32(const void* p) {
    return (uint32_t)__cvta_generic_to_shared(p);
}
__device__ __forceinline__ void mma16816(float* c, const uint32_t* a, const uint32_t* b) {
    asm volatile(
        "mma.sync.aligned.m16n8k16.row.col.f32.bf16.bf16.f32 "
        "{%0,%1,%2,%3}, {%4,%5,%6,%7}, {%8,%9}, {%0,%1,%2,%3};"
        : "+f"(c[0]), "+f"(c[1]), "+f"(c[2]), "+f"(c[3])
        : "r"(a[0]), "r"(a[1]), "r"(a[2]), "r"(a[3]), "r"(b[0]), "r"(b[1]));
}
__device__ __forceinline__ void ldsm4(uint32_t* r, uint32_t addr) {
    asm volatile("ldmatrix.sync.aligned.m8n8.x4.shared.b16 {%0,%1,%2,%3}, [%4];"
                 : "=r"(r[0]), "=r"(r[1]), "=r"(r[2]), "=r"(r[3]) : "r"(addr));
}

// Padded row stride 136 halves (272 B): ldmatrix / STS rows hit distinct bank
// quads (68 mod 32 = 4), conflict-free.
#define SH 136
#define TILE_B (128 * SH * 2)            // 34816 B : one weight tile (hi or lo)
#define TILE_A (64 * SH * 2)             // 17408 B : one A/Y tile (hi or lo)
#define OFF_A   (4 * TILE_B)             // 139264 : A/Y hi
#define OFF_AL  (OFF_A + TILE_A)         // A/Y lo
#define OFF_BIAS (OFF_A + 2 * TILE_A)    // 174080
#define SMEM_FUSED (OFF_BIAS + 1024)     // 175104 B

// ---------------------------------------------------------------------------
// Kernel 1: zero aggregation buffer + BN stats
// ---------------------------------------------------------------------------
__global__ void k_zero(int n4) {
    int i = blockIdx.x * blockDim.x + threadIdx.x;
    if (i < n4) reinterpret_cast<float4*>(g_agg)[i] = make_float4(0.f, 0.f, 0.f, 0.f);
    if (blockIdx.x == 0 && threadIdx.x < 2 * D) g_stats[threadIdx.x] = 0.0f;
}

// ---------------------------------------------------------------------------
// Kernel 2: transpose + bf16-split both weight matrices (one-shot, tiny)
// ---------------------------------------------------------------------------
__global__ void k_wt(const float* __restrict__ W1, const float* __restrict__ W2) {
    int i = blockIdx.x * 256 + threadIdx.x;
    if (i < D * D) {
        int k = i >> 7, c = i & 127;
        float w1 = W1[i], w2 = W2[i];
        __nv_bfloat16 h1 = __float2bfloat16(w1);
        __nv_bfloat16 h2 = __float2bfloat16(w2);
        g_w1tH[c * D + k] = h1;
        g_w1tL[c * D + k] = __float2bfloat16(w1 - __bfloat162float(h1));
        g_w2tH[c * D + k] = h2;
        g_w2tL[c * D + k] = __float2bfloat16(w2 - __bfloat162float(h2));
    }
}

// ---------------------------------------------------------------------------
// Kernel 3: scatter-add. One warp per edge; red.global.add.v4.f32 per lane.
// ---------------------------------------------------------------------------
__global__ void k_scatter(const float* __restrict__ feat,
                          const int* __restrict__ ei, int E) {
    int gw = (blockIdx.x * blockDim.x + threadIdx.x) >> 5;
    int lane = threadIdx.x & 31;
    if (gw >= E) return;
    int src = __ldg(ei + gw);
    int dst = __ldg(ei + E + gw);
    const float4 v = reinterpret_cast<const float4*>(feat + (size_t)src * D)[lane];
    float* p = g_agg + (size_t)dst * D + lane * 4;
    asm volatile("red.global.add.v4.f32 [%0], {%1, %2, %3, %4};"
                 :: "l"(p), "f"(v.x), "f"(v.y), "f"(v.z), "f"(v.w)
                 : "memory");
}

// ---------------------------------------------------------------------------
// Kernel 4: persistent fused MLP. Per 64-row tile:
//   A = feat+agg -> bf16 hi/lo in SMEM -> GEMM1 (3 passes vs W1 hi/lo)
//   -> y1 = relu(.+b1) split IN PLACE over the A tile (never hits global)
//   -> GEMM2 (3 passes vs W2 hi/lo) -> out = relu(.+b2) + fused BN stats.
// Weights (4 x 34 KB) loaded once per CTA; grid = #SMs, 1 CTA/SM.
// 8 warps: warpM = wid&1 (32-row halves), warpN = wid>>1 (32-col quarters).
// ---------------------------------------------------------------------------
__global__ __launch_bounds__(256, 1)
void k_fused(const float* __restrict__ feat,
             const float* __restrict__ b1, const float* __restrict__ b2,
             float* __restrict__ outF, int M, int nTiles) {
    extern __shared__ __align__(16) uint8_t smem[];
    const uint32_t sBase = smem_u32(smem);
    uint16_t* sAh = reinterpret_cast<uint16_t*>(smem + OFF_A);
    uint16_t* sAl = reinterpret_cast<uint16_t*>(smem + OFF_AL);
    float* s_b1 = reinterpret_cast<float*>(smem + OFF_BIAS);
    float* s_b2 = s_b1 + D;

    const int tid = threadIdx.x;
    const int wid = tid >> 5;
    const int lane = tid & 31;
    const int g = lane >> 2;
    const int l4 = lane & 3;
    const int warpM = wid & 1;
    const int warpN = wid >> 1;

    if (tid < D) s_b1[tid] = b1[tid];
    else         s_b2[tid - D] = b2[tid - D];

    // ---- Load all 4 weight tiles once (cp.async) ----
#pragma unroll
    for (int t = 0; t < 8; ++t) {
        int idx = tid + t * 256;            // 0..2047 = 128 rows x 16 chunks
        int row = idx >> 4;
        int kb = (idx & 15) * 16;
        uint32_t dOff = (uint32_t)(row * (SH * 2) + kb);
        size_t gOff = (size_t)row * 256 + kb;
        cp16(sBase + dOff,              (const uint8_t*)g_w1tH + gOff);
        cp16(sBase + TILE_B + dOff,     (const uint8_t*)g_w1tL + gOff);
        cp16(sBase + 2 * TILE_B + dOff, (const uint8_t*)g_w2tH + gOff);
        cp16(sBase + 3 * TILE_B + dOff, (const uint8_t*)g_w2tL + gOff);
    }
    cp_commit();
    cp_wait<0>();

    // ---- ldmatrix fragment offsets (bytes, relative to tile bases) ----
    uint32_t aOff[2];
#pragma unroll
    for (int mi = 0; mi < 2; ++mi) {
        int arow = warpM * 32 + mi * 16 + (lane & 7) + ((lane >> 3) & 1) * 8;
        int akoff = (lane >> 4) * 8;
        aOff[mi] = (uint32_t)((arow * SH + akoff) * 2);
    }
    uint32_t bOff[2];
#pragma unroll
    for (int pr = 0; pr < 2; ++pr) {
        int brow = warpN * 32 + pr * 16 + (lane & 7) + (lane >> 4) * 8;
        int bkoff = ((lane >> 3) & 1) * 8;
        bOff[pr] = (uint32_t)((brow * SH + bkoff) * 2);
    }

    // BN stats accumulated across all tiles in registers
    float cs[4][2], cq[4][2];
#pragma unroll
    for (int ni = 0; ni < 4; ++ni) {
        cs[ni][0] = cs[ni][1] = 0.f;
        cq[ni][0] = cq[ni][1] = 0.f;
    }

    float c[2][4][4];

    // mainloop helper: 3-pass split GEMM from (aHi,aLo) x (bHi,bLo) tile bases
    auto runGemm = [&](uint32_t aHi, uint32_t aLo, uint32_t bHi, uint32_t bLo) {
#pragma unroll
        for (int mi = 0; mi < 2; ++mi)
#pragma unroll
            for (int ni = 0; ni < 4; ++ni)
#pragma unroll
                for (int e = 0; e < 4; ++e) c[mi][ni][e] = 0.f;
#pragma unroll
        for (int pass = 0; pass < 3; ++pass) {
            const uint32_t aBase = (pass == 2 ? aLo : aHi);
            const uint32_t bBase = (pass == 1 ? bLo : bHi);
#pragma unroll
            for (int ks = 0; ks < 8; ++ks) {
                uint32_t a[2][4], b[2][4];
                ldsm4(a[0], aBase + aOff[0] + ks * 32);
                ldsm4(a[1], aBase + aOff[1] + ks * 32);
                ldsm4(b[0], bBase + bOff[0] + ks * 32);
                ldsm4(b[1], bBase + bOff[1] + ks * 32);
#pragma unroll
                for (int mi = 0; mi < 2; ++mi) {
                    mma16816(c[mi][0], a[mi], &b[0][0]);
                    mma16816(c[mi][1], a[mi], &b[0][2]);
                    mma16816(c[mi][2], a[mi], &b[1][0]);
                    mma16816(c[mi][3], a[mi], &b[1][2]);
                }
            }
        }
    };

    for (int t = blockIdx.x; t < nTiles; t += gridDim.x) {
        const int rowBase = t * 64;

        __syncthreads();   // previous tile's GEMM2 reads of sA/sY complete

        // ---- A tile: feat + agg -> bf16 hi/lo split -> SMEM ----
#pragma unroll
        for (int tt = 0; tt < 4; ++tt) {
            int idx = tid + tt * 256;       // 64 rows x 16 chunks of 8 floats
            int row = idx >> 4;
            int kc = (idx & 15) * 8;
            int grow = rowBase + row;
            float h[8];
            if (grow < M) {
                const float4* fp = reinterpret_cast<const float4*>(feat + (size_t)grow * D + kc);
                const float4* ap = reinterpret_cast<const float4*>(g_agg + (size_t)grow * D + kc);
                float4 f0 = fp[0], f1 = fp[1], a0 = ap[0], a1 = ap[1];
                h[0] = f0.x + a0.x; h[1] = f0.y + a0.y; h[2] = f0.z + a0.z; h[3] = f0.w + a0.w;
                h[4] = f1.x + a1.x; h[5] = f1.y + a1.y; h[6] = f1.z + a1.z; h[7] = f1.w + a1.w;
            } else {
#pragma unroll
                for (int e = 0; e < 8; ++e) h[e] = 0.f;
            }
            uint4 hv, lv;
            uint32_t* hp = reinterpret_cast<uint32_t*>(&hv);
            uint32_t* lp = reinterpret_cast<uint32_t*>(&lv);
#pragma unroll
            for (int e = 0; e < 4; ++e) {
                __nv_bfloat162 hh = __floats2bfloat162_rn(h[2 * e], h[2 * e + 1]);
                __nv_bfloat162 ll = __floats2bfloat162_rn(
                    h[2 * e] - __bfloat162float(hh.x),
                    h[2 * e + 1] - __bfloat162float(hh.y));
                hp[e] = *reinterpret_cast<uint32_t*>(&hh);
                lp[e] = *reinterpret_cast<uint32_t*>(&ll);
            }
            *reinterpret_cast<uint4*>(&sAh[row * SH + kc]) = hv;
            *reinterpret_cast<uint4*>(&sAl[row * SH + kc]) = lv;
        }
        __syncthreads();

        // ---- GEMM1: A x W1 ----
        runGemm(sBase + OFF_A, sBase + OFF_AL, sBase, sBase + TILE_B);
        __syncthreads();   // all reads of sA done before overwrite with y1

        // ---- Epilogue 1: y1 = relu(c + b1), split, write over sA ----
#pragma unroll
        for (int mi = 0; mi < 2; ++mi) {
#pragma unroll
            for (int half = 0; half < 2; ++half) {
                const int lrow = warpM * 32 + mi * 16 + g + half * 8;
#pragma unroll
                for (int ni = 0; ni < 4; ++ni) {
                    const int col = warpN * 32 + ni * 8 + 2 * l4;
                    float v0 = fmaxf(c[mi][ni][half * 2 + 0] + s_b1[col], 0.f);
                    float v1 = fmaxf(c[mi][ni][half * 2 + 1] + s_b1[col + 1], 0.f);
                    __nv_bfloat16 h0 = __float2bfloat16(v0);
                    __nv_bfloat16 h1 = __float2bfloat16(v1);
                    __nv_bfloat162 hh; hh.x = h0; hh.y = h1;
                    __nv_bfloat162 ll = __floats2bfloat162_rn(
                        v0 - __bfloat162float(h0), v1 - __bfloat162float(h1));
                    *reinterpret_cast<uint32_t*>(&sAh[lrow * SH + col]) =
                        *reinterpret_cast<uint32_t*>(&hh);
                    *reinterpret_cast<uint32_t*>(&sAl[lrow * SH + col]) =
                        *reinterpret_cast<uint32_t*>(&ll);
                }
            }
        }
        __syncthreads();

        // ---- GEMM2: y1 x W2 ----
        runGemm(sBase + OFF_A, sBase + OFF_AL,
                sBase + 2 * TILE_B, sBase + 3 * TILE_B);

        // ---- Epilogue 2: out = relu(c + b2) -> global + BN stats ----
#pragma unroll
        for (int mi = 0; mi < 2; ++mi) {
#pragma unroll
            for (int half = 0; half < 2; ++half) {
                const int row = rowBase + warpM * 32 + mi * 16 + g + half * 8;
                if (row < M) {
#pragma unroll
                    for (int ni = 0; ni < 4; ++ni) {
                        const int col = warpN * 32 + ni * 8 + 2 * l4;
                        float v0 = fmaxf(c[mi][ni][half * 2 + 0] + s_b2[col], 0.f);
                        float v1 = fmaxf(c[mi][ni][half * 2 + 1] + s_b2[col + 1], 0.f);
                        float2 st; st.x = v0; st.y = v1;
                        *reinterpret_cast<float2*>(outF + (size_t)row * D + col) = st;
                        cs[ni][0] += v0; cs[ni][1] += v1;
                        cq[ni][0] += v0 * v0; cq[ni][1] += v1 * v1;
                    }
                }
            }
        }
    }

    // ---- Final BN stats reduction (once per CTA) ----
#pragma unroll
    for (int off = 4; off < 32; off <<= 1) {
#pragma unroll
        for (int ni = 0; ni < 4; ++ni) {
#pragma unroll
            for (int e = 0; e < 2; ++e) {
                cs[ni][e] += __shfl_xor_sync(0xFFFFFFFFu, cs[ni][e], off);
                cq[ni][e] += __shfl_xor_sync(0xFFFFFFFFu, cq[ni][e], off);
            }
        }
    }
    __syncthreads();                      // sA region dead -> reduction buffer
    float* redS = reinterpret_cast<float*>(smem + OFF_A);    // [8][32]
    float* redQ = redS + 256;
    if (g == 0) {
#pragma unroll
        for (int ni = 0; ni < 4; ++ni) {
#pragma unroll
            for (int e = 0; e < 2; ++e) {
                int cc = ni * 8 + 2 * l4 + e;
                redS[wid * 32 + cc] = cs[ni][e];
                redQ[wid * 32 + cc] = cq[ni][e];
            }
        }
    }
    __syncthreads();
    if (tid < 128) {
        int wN = tid >> 5;
        int cc = tid & 31;
        float s = 0.f, q = 0.f;
#pragma unroll
        for (int w = 0; w < 2; ++w) {     // wid = wN*2 + warpM
            s += redS[(wN * 2 + w) * 32 + cc];
            q += redQ[(wN * 2 + w) * 32 + cc];
        }
        atomicAdd(&g_stats[tid], s);
        atomicAdd(&g_stats[D + tid], q);
    }
}

// ---------------------------------------------------------------------------
// Kernel 5: (sum, sumsq) -> (scale, shift)
// ---------------------------------------------------------------------------
__global__ void k_finalize(const float* __restrict__ gamma,
                           const float* __restrict__ beta, float invN) {
    int c = threadIdx.x;
    float mean = g_stats[c] * invN;
    float var = g_stats[D + c] * invN - mean * mean;
    float scale = gamma[c] * rsqrtf(var + 1e-5f);
    g_stats[c] = scale;
    g_stats[D + c] = beta[c] - mean * scale;
}

// ---------------------------------------------------------------------------
// Kernel 6: out = out * scale[col] + shift[col], in place
// ---------------------------------------------------------------------------
__global__ void k_norm(float4* __restrict__ out, int n4) {
    int i = blockIdx.x * blockDim.x + threadIdx.x;
    if (i >= n4) return;
    int c4 = (i & 31) * 4;
    float4 sc = *reinterpret_cast<const float4*>(&g_stats[c4]);
    float4 sh = *reinterpret_cast<const float4*>(&g_stats[D + c4]);
    float4 v = out[i];
    v.x = v.x * sc.x + sh.x;
    v.y = v.y * sc.y + sh.y;
    v.z = v.z * sc.z + sh.z;
    v.w = v.w * sc.w + sh.w;
    out[i] = v;
}

// ---------------------------------------------------------------------------
extern "C" void kernel_launch(void* const* d_in, const int* in_sizes, int n_in,
                              void* d_out, int out_size) {
    const float* feat  = (const float*)d_in[0];
    const int*   ei    = (const int*)d_in[1];
    const float* W1    = (const float*)d_in[2];
    const float* b1    = (const float*)d_in[3];
    const float* W2    = (const float*)d_in[4];
    const float* b2    = (const float*)d_in[5];
    const float* gamma = (const float*)d_in[6];
    const float* beta  = (const float*)d_in[7];
    float* out = (float*)d_out;

    const int N = in_sizes[0] / D;     // 50000
    const int E = in_sizes[1] / 2;     // 600000
    const int n4 = N * D / 4;

    int sms = 148;
    cudaDeviceGetAttribute(&sms, cudaDevAttrMultiProcessorCount, 0);

    cudaFuncSetAttribute(k_fused, cudaFuncAttributeMaxDynamicSharedMemorySize, SMEM_FUSED);

    k_zero<<<(n4 + 255) / 256, 256>>>(n4);
    k_wt<<<(D * D + 255) / 256, 256>>>(W1, W2);
    {
        long long totalThreads = (long long)E * 32;
        int blocks = (int)((totalThreads + 255) / 256);
        k_scatter<<<blocks, 256>>>(feat, ei, E);
    }
    k_fused<<<sms, 256, SMEM_FUSED>>>(feat, b1, b2, out, N, (N + 63) / 64);
    k_finalize<<<1, 128>>>(gamma, beta, 1.0f / (float)N);
    k_norm<<<(n4 + 255) / 256, 256>>>((float4*)out, n4);
}